// round 15
// baseline (speedup 1.0000x reference)
#include <cuda_runtime.h>
#include <cstdint>

#define NPTS  4096
#define BATCH 8
#define KNN_K 16

// scratch: neighbor indices (original within-batch indices), 2MB
__device__ int g_idx[BATCH * NPTS * KNN_K];
// scratch: pooled features, 96 floats per point packed as 48 u64, 12.6MB
__device__ __align__(16) unsigned long long g_feat[BATCH * NPTS * 48];

// ---------------------------------------------------------------------------
// packed f32x2 helpers
// ---------------------------------------------------------------------------
__device__ __forceinline__ unsigned long long ffma2(unsigned long long a,
                                                    unsigned long long b,
                                                    unsigned long long c) {
    unsigned long long d;
    asm("fma.rn.f32x2 %0, %1, %2, %3;" : "=l"(d) : "l"(a), "l"(b), "l"(c));
    return d;
}
__device__ __forceinline__ unsigned long long add2(unsigned long long a,
                                                   unsigned long long b) {
    unsigned long long d;
    asm("add.rn.f32x2 %0, %1, %2;" : "=l"(d) : "l"(a), "l"(b));
    return d;
}
__device__ __forceinline__ unsigned long long mul2(unsigned long long a,
                                                   unsigned long long b) {
    unsigned long long d;
    asm("mul.rn.f32x2 %0, %1, %2;" : "=l"(d) : "l"(a), "l"(b));
    return d;
}
__device__ __forceinline__ unsigned long long pack2(float lo, float hi) {
    unsigned long long p;
    asm("mov.b64 %0, {%1, %2};" : "=l"(p) : "f"(lo), "f"(hi));
    return p;
}
__device__ __forceinline__ void unpack2(unsigned long long p, float& lo, float& hi) {
    asm("mov.b64 {%0, %1}, %2;" : "=f"(lo), "=f"(hi) : "l"(p));
}

// sorted u64 lower-half bitonic merge: a (sorted asc) x b (sorted asc) -> a
__device__ __forceinline__ void merge16(unsigned long long* a,
                                        const unsigned long long* bsrc) {
    unsigned long long L[KNN_K];
#pragma unroll
    for (int i = 0; i < KNN_K; ++i) {
        unsigned long long bb = bsrc[KNN_K - 1 - i];
        L[i] = (a[i] < bb) ? a[i] : bb;
    }
#pragma unroll
    for (int j = 8; j >= 1; j >>= 1) {
#pragma unroll
        for (int i = 0; i < KNN_K; ++i) {
            if ((i & j) == 0) {
                unsigned long long lo = L[i], hi = L[i | j];
                unsigned long long mn = (lo < hi) ? lo : hi;
                unsigned long long mx = (lo < hi) ? hi : lo;
                L[i] = mn; L[i | j] = mx;
            }
        }
    }
#pragma unroll
    for (int i = 0; i < KNN_K; ++i) a[i] = L[i];
}

// ---------------------------------------------------------------------------
// Kernel 1: exact KNN, 4 threads/query (quarter ranges), buffered top-16.
// (byte-identical to the validated round-12 version)
// ---------------------------------------------------------------------------
#define QCAP 16   // per-lane FIFO capacity (u32 entries)

extern "C" __global__ void __launch_bounds__(256)
knn_kernel(const float* __restrict__ x) {
    extern __shared__ __align__(16) char smem_raw[];
    float2* sxy = (float2*)smem_raw;                                   // 32KB
    float*  ssq = (float*)(smem_raw + NPTS * 8);                       // 16KB
    unsigned long long* mbuf =
        (unsigned long long*)(smem_raw + NPTS * 12);                   // 3*64*17*8
    unsigned* qbuf = (unsigned*)(mbuf + 3 * 64 * 17);                  // 16KB

    const int tid = threadIdx.x;
    const int b   = blockIdx.y;
    const float2* __restrict__ xb = ((const float2*)x) + (size_t)b * NPTS;

    for (int i = tid; i < NPTS; i += 256) {
        float2 v = xb[i];
        sxy[i] = v;
        ssq[i] = __fadd_rn(__fmul_rn(v.x, v.x), __fmul_rn(v.y, v.y));
    }
    __syncthreads();

    const int qloc = tid & 63;
    const int part = tid >> 6;                    // warp-uniform (2 warps/part)
    const int q    = blockIdx.x * 64 + qloc;
    const float2 qv = sxy[q];
    const float qx = qv.x, qy = qv.y, qsq = ssq[q];

    // sentinel = mapped(+INF); unmaps to float +INF for the threshold
    unsigned bu[KNN_K];
    int      bi[KNN_K];
#pragma unroll
    for (int s = 0; s < KNN_K; ++s) { bu[s] = 0xFF800000u; bi[s] = 0; }

    const int jbeg = part * (NPTS / 4);
    int cnt = 0;
    float worstf = __int_as_float(0x7F800000);    // +INF

    auto insert = [&](unsigned u, int j) {
        bool c[KNN_K];
#pragma unroll
        for (int s = 0; s < KNN_K; ++s) c[s] = (u < bu[s]);
#pragma unroll
        for (int s = KNN_K - 1; s >= 1; --s) {
            bu[s] = c[s - 1] ? bu[s - 1] : (c[s] ? u : bu[s]);
            bi[s] = c[s - 1] ? bi[s - 1] : (c[s] ? j : bi[s]);
        }
        if (c[0]) { bu[0] = u; bi[0] = j; }
    };

    auto drain = [&]() {
#pragma unroll 1
        for (int t = 0; t < cnt; ++t) {           // divergent per-lane count
            int j = (int)qbuf[t * 256 + tid];
            float2 p = sxy[j];
            float ps = ssq[j];
            // exact reference formula, no FMA contraction
            float dot = __fadd_rn(__fmul_rn(qx, p.x), __fmul_rn(qy, p.y));
            float d   = __fsub_rn(__fadd_rn(qsq, ps), __fmul_rn(2.0f, dot));
            int ib = __float_as_int(d);
            unsigned u = (ib >= 0) ? ((unsigned)ib ^ 0x80000000u) : ~(unsigned)ib;
            if (u < bu[KNN_K - 1]) insert(u, j);
        }
        cnt = 0;
        // unmap bu[15] -> float threshold (sentinel -> +INF)
        unsigned u15 = bu[KNN_K - 1];
        int ib = (u15 & 0x80000000u) ? (int)(u15 ^ 0x80000000u) : (int)~u15;
        worstf = __int_as_float(ib);
    };

    const unsigned long long qx2 = pack2(qx, qx);
    const unsigned long long qy2 = pack2(qy, qy);
    const unsigned long long qs2 = pack2(qsq, qsq);
    const unsigned long long n22 = pack2(-2.0f, -2.0f);

#pragma unroll 1
    for (int blk = 0; blk < NPTS / 4; blk += 8) {
#pragma unroll
        for (int pp = 0; pp < 4; ++pp) {
            const int j = jbeg + blk + pp * 2;
            float4 pxy = *(const float4*)(sxy + j);        // x0,y0,x1,y1
            float2 ps  = *(const float2*)(ssq + j);
            unsigned long long px  = pack2(pxy.x, pxy.z);
            unsigned long long py  = pack2(pxy.y, pxy.w);
            unsigned long long psq = pack2(ps.x, ps.y);
            // per-half identical rounding to the scalar reference:
            unsigned long long dot = add2(mul2(qx2, px), mul2(qy2, py));
            unsigned long long dv  = add2(add2(qs2, psq), mul2(n22, dot));
            float d0, d1; unpack2(dv, d0, d1);
            if (d0 < worstf) { qbuf[cnt * 256 + tid] = (unsigned)j;       ++cnt; }
            if (d1 < worstf) { qbuf[cnt * 256 + tid] = (unsigned)(j + 1); ++cnt; }
        }
        if (__any_sync(0xFFFFFFFFu, cnt >= QCAP - 8)) drain();
    }
    drain();                                      // leftovers

    // parts 1..3 publish their sorted lists
    if (part != 0) {
        unsigned long long* dst = mbuf + ((part - 1) * 64 + qloc) * 17;
#pragma unroll
        for (int s = 0; s < KNN_K; ++s)
            dst[s] = ((unsigned long long)bu[s] << 32) | (unsigned)bi[s];
    }
    __syncthreads();

    if (part == 0) {
        unsigned long long L[KNN_K];
#pragma unroll
        for (int s = 0; s < KNN_K; ++s)
            L[s] = ((unsigned long long)bu[s] << 32) | (unsigned)bi[s];

        merge16(L, mbuf + (0 * 64 + qloc) * 17);
        unsigned long long M[KNN_K];
        const unsigned long long* p2 = mbuf + (1 * 64 + qloc) * 17;
#pragma unroll
        for (int s = 0; s < KNN_K; ++s) M[s] = p2[s];
        merge16(M, mbuf + (2 * 64 + qloc) * 17);
        merge16(L, M);

        int* outp = g_idx + ((size_t)b * NPTS + q) * KNN_K;
#pragma unroll
        for (int s = 0; s < KNN_K; ++s)
            outp[s] = (int)(L[s] & 0xFFFFFFFFu);
    }
}

// ---------------------------------------------------------------------------
// Kernel 2a: pooling, 4-way feature split with FULLY STATIC facc indexing.
// part 0: pools (u64 0..15) + L4 pairs 0..3   (u64 16..19)   ~448 instr/nbr
// part 1: L4 pairs 4..12                      (u64 20..28)   ~493
// part 2: L4 pairs 13..21                     (u64 29..37)   ~493
// part 3: L4 pairs 22..31                     (u64 38..47)   ~510
// All facc indices are compile-time constants -> registers (the round-12
// version's runtime fi forced facc into local memory -> LDL/STL per access).
// Accumulation order per feature unchanged -> bit-identical g_feat.
// ---------------------------------------------------------------------------
struct __align__(16) SmemPool {
    float2 pts[NPTS];          // 32KB
    float w1[32];              // [8][4]
    float w2[64];              // [8][8]
    float w3[128];             // [16][8]
    float w4[1024];            // [64][16]
    float mw[64];              // [4][16]
    float mb[4];
    float s1[8],  b1[8];
    float s2[8],  b2[8];
    float s3[16], b3[16];
    float s4[64], b4[64];
};

template<int PART>
__device__ __forceinline__ void pool_body(const SmemPool* sm,
                                          const int* __restrict__ gi,
                                          float2 ctr, int gq) {
    constexpr int PBEG = (PART == 0) ? 0 : (PART == 1) ? 4 : (PART == 2) ? 13 : 22;
    constexpr int PEND = (PART == 0) ? 4 : (PART == 1) ? 13 : (PART == 2) ? 22 : 32;
    constexpr int NP   = PEND - PBEG;                    // L4 pairs this part
    constexpr int POOLN = (PART == 0) ? 16 : 0;          // pooled u64 slots
    constexpr int NF   = POOLN + NP;

    unsigned long long facc[NF];
#pragma unroll
    for (int i = 0; i < NF; ++i) facc[i] = 0ULL;

#pragma unroll 1
    for (int k = 0; k < KNN_K; ++k) {
        const int nbk = gi[k];
        const float2 P = sm->pts[nbk];
        const unsigned long long m3p = pack2(sm->mw[32 + k], sm->mw[32 + k]);
        const unsigned long long m4p = pack2(sm->mw[48 + k], sm->mw[48 + k]);

        // layer 1: 4 -> 8
        float h1[8];
#pragma unroll
        for (int o = 0; o < 8; o += 2) {
#pragma unroll
            for (int t = 0; t < 2; ++t) {
                float4 w = *(const float4*)(sm->w1 + (o + t) * 4);
                float v = P.x * w.x + P.y * w.y + ctr.x * w.z + ctr.y * w.w;
                h1[o + t] = fmaxf(fmaf(v, sm->s1[o + t], sm->b1[o + t]), 0.0f);
            }
            if (PART == 0) {
                const unsigned long long m1p = pack2(sm->mw[k], sm->mw[k]);
                facc[o / 2] = ffma2(pack2(h1[o], h1[o + 1]), m1p, facc[o / 2]);
            }
        }
        // layer 2: 8 -> 8
        float h2[8];
#pragma unroll
        for (int o = 0; o < 8; o += 2) {
#pragma unroll
            for (int t = 0; t < 2; ++t) {
                const float4* w = (const float4*)(sm->w2 + (o + t) * 8);
                float4 wa = w[0], wb = w[1];
                float v = h1[0] * wa.x + h1[1] * wa.y + h1[2] * wa.z + h1[3] * wa.w
                        + h1[4] * wb.x + h1[5] * wb.y + h1[6] * wb.z + h1[7] * wb.w;
                h2[o + t] = fmaxf(fmaf(v, sm->s2[o + t], sm->b2[o + t]), 0.0f);
            }
            if (PART == 0) {
                const unsigned long long m2p = pack2(sm->mw[16 + k], sm->mw[16 + k]);
                facc[4 + o / 2] = ffma2(pack2(h2[o], h2[o + 1]), m2p, facc[4 + o / 2]);
            }
        }
        // layer 3: 8 -> 16 (packed pairs for layer-4 dots)
        unsigned long long h3p[8];
#pragma unroll
        for (int o = 0; o < 16; o += 2) {
            float vv[2];
#pragma unroll
            for (int t = 0; t < 2; ++t) {
                const float4* w = (const float4*)(sm->w3 + (o + t) * 8);
                float4 wa = w[0], wb = w[1];
                float v = h2[0] * wa.x + h2[1] * wa.y + h2[2] * wa.z + h2[3] * wa.w
                        + h2[4] * wb.x + h2[5] * wb.y + h2[6] * wb.z + h2[7] * wb.w;
                vv[t] = fmaxf(fmaf(v, sm->s3[o + t], sm->b3[o + t]), 0.0f);
            }
            h3p[o / 2] = pack2(vv[0], vv[1]);
            if (PART == 0)
                facc[8 + o / 2] = ffma2(h3p[o / 2], m3p, facc[8 + o / 2]);
        }
        // layer 4: this part's pairs, FULLY UNROLLED (static facc indices)
#pragma unroll
        for (int pp = 0; pp < NP; ++pp) {
            const int o = (PBEG + pp) * 2;
            float vv[2];
#pragma unroll
            for (int t = 0; t < 2; ++t) {
                const ulonglong2* wrow = (const ulonglong2*)(sm->w4 + (o + t) * 16);
                ulonglong2 wa = wrow[0], wb = wrow[1], wc = wrow[2], wd = wrow[3];
                unsigned long long acc = ffma2(h3p[0], wa.x, 0ULL);
                acc = ffma2(h3p[1], wa.y, acc);
                acc = ffma2(h3p[2], wb.x, acc);
                acc = ffma2(h3p[3], wb.y, acc);
                acc = ffma2(h3p[4], wc.x, acc);
                acc = ffma2(h3p[5], wc.y, acc);
                acc = ffma2(h3p[6], wd.x, acc);
                acc = ffma2(h3p[7], wd.y, acc);
                float lo, hi; unpack2(acc, lo, hi);
                float v = lo + hi;
                vv[t] = fmaxf(fmaf(v, sm->s4[o + t], sm->b4[o + t]), 0.0f);
            }
            facc[POOLN + pp] = ffma2(pack2(vv[0], vv[1]), m4p, facc[POOLN + pp]);
        }
    }

    // mlp biases (static per part)
    {
        const unsigned long long c3 = pack2(sm->mb[3], sm->mb[3]);
        if (PART == 0) {
            const unsigned long long c0 = pack2(sm->mb[0], sm->mb[0]);
            const unsigned long long c1 = pack2(sm->mb[1], sm->mb[1]);
            const unsigned long long c2 = pack2(sm->mb[2], sm->mb[2]);
#pragma unroll
            for (int i = 0; i < 4; ++i)  facc[i]     = add2(facc[i], c0);
#pragma unroll
            for (int i = 0; i < 4; ++i)  facc[4 + i] = add2(facc[4 + i], c1);
#pragma unroll
            for (int i = 0; i < 8; ++i)  facc[8 + i] = add2(facc[8 + i], c2);
#pragma unroll
            for (int i = 0; i < NP; ++i) facc[16 + i] = add2(facc[16 + i], c3);
        } else {
#pragma unroll
            for (int i = 0; i < NF; ++i) facc[i] = add2(facc[i], c3);
        }
    }

    constexpr int OFF = (PART == 0) ? 0 : 16 + PBEG;     // u64 offset in row
    unsigned long long* dst = g_feat + (size_t)gq * 48 + OFF;
#pragma unroll
    for (int i = 0; i < NF; ++i) dst[i] = facc[i];
}

extern "C" __global__ void __launch_bounds__(256, 2)
pool_kernel(const float* __restrict__ x,
            const float* __restrict__ w1, const float* __restrict__ w2,
            const float* __restrict__ w3, const float* __restrict__ w4,
            const float* __restrict__ mw, const float* __restrict__ mb,
            const float* __restrict__ bn1, const float* __restrict__ bn2,
            const float* __restrict__ bn3, const float* __restrict__ bn4) {
    extern __shared__ __align__(16) char smem_raw[];
    SmemPool* sm = (SmemPool*)smem_raw;

    const int tid = threadIdx.x;
    const int b   = blockIdx.y;

    for (int i = tid; i < NPTS; i += 256) sm->pts[i] = ((const float2*)x)[(size_t)b * NPTS + i];
    for (int i = tid; i < 32;   i += 256) sm->w1[i] = w1[i];
    for (int i = tid; i < 64;   i += 256) sm->w2[i] = w2[i];
    for (int i = tid; i < 128;  i += 256) sm->w3[i] = w3[i];
    for (int i = tid; i < 1024; i += 256) sm->w4[i] = w4[i];
    for (int i = tid; i < 64;   i += 256) sm->mw[i] = mw[i];
    if (tid < 4) sm->mb[tid] = mb[tid];
    for (int i = tid; i < 8;  i += 256) {
        float s = bn1[i] * rsqrtf(bn1[24 + i] + 1e-5f);
        sm->s1[i] = s; sm->b1[i] = bn1[8 + i] - bn1[16 + i] * s;
        float t = bn2[i] * rsqrtf(bn2[24 + i] + 1e-5f);
        sm->s2[i] = t; sm->b2[i] = bn2[8 + i] - bn2[16 + i] * t;
    }
    for (int i = tid; i < 16; i += 256) {
        float s = bn3[i] * rsqrtf(bn3[48 + i] + 1e-5f);
        sm->s3[i] = s; sm->b3[i] = bn3[16 + i] - bn3[32 + i] * s;
    }
    for (int i = tid; i < 64; i += 256) {
        float s = bn4[i] * rsqrtf(bn4[192 + i] + 1e-5f);
        sm->s4[i] = s; sm->b4[i] = bn4[64 + i] - bn4[128 + i] * s;
    }
    __syncthreads();

    const int nloc = tid & 63;
    const int part = tid >> 6;                    // warp-uniform
    const int n    = blockIdx.x * 64 + nloc;
    const int gq   = b * NPTS + n;
    const int* __restrict__ gi = g_idx + (size_t)gq * KNN_K;
    const float2 ctr = sm->pts[n];

    if      (part == 0) pool_body<0>(sm, gi, ctr, gq);
    else if (part == 1) pool_body<1>(sm, gi, ctr, gq);
    else if (part == 2) pool_body<2>(sm, gi, ctr, gq);
    else                pool_body<3>(sm, gi, ctr, gq);
}

// ---------------------------------------------------------------------------
// Kernel 2b: final 96x96 GEMM + BN/ReLU + L2 normalize
// (byte-identical to rounds 6-12)
// ---------------------------------------------------------------------------
struct __align__(16) SmemGemm {
    float w5[9216];            // [96][96]
    float s5[96], b5[96];
};

extern "C" __global__ void __launch_bounds__(128)
gemm_kernel(const float* __restrict__ w5, const float* __restrict__ bn5,
            float* __restrict__ out) {
    extern __shared__ __align__(16) char smem_raw[];
    SmemGemm* sm = (SmemGemm*)smem_raw;

    const int tid = threadIdx.x;
    const int b   = blockIdx.y;

    for (int i = tid; i < 9216; i += 128) sm->w5[i] = w5[i];
    for (int i = tid; i < 96; i += 128) {
        float s = bn5[i] * rsqrtf(bn5[288 + i] + 1e-5f);
        sm->s5[i] = s; sm->b5[i] = bn5[96 + i] - bn5[192 + i] * s;
    }
    __syncthreads();

    const int half = tid & 1;
    const int n    = blockIdx.x * 64 + (tid >> 1);
    const int gq   = b * NPTS + n;

    unsigned long long fh[24];
    const ulonglong2* fsrc = (const ulonglong2*)(g_feat + (size_t)gq * 48 + half * 24);
#pragma unroll
    for (int i = 0; i < 12; ++i) {
        ulonglong2 t = fsrc[i];
        fh[2 * i] = t.x; fh[2 * i + 1] = t.y;
    }

    const int obase = half * 48;
    float* __restrict__ mybase = out + (size_t)gq * 96 + obase;
    float ss = 0.0f;

#pragma unroll 1
    for (int o = 0; o < 96; ++o) {
        const ulonglong2* wrow = (const ulonglong2*)(sm->w5 + o * 96 + half * 48);
        unsigned long long a0 = 0ULL, a1 = 0ULL;
#pragma unroll
        for (int j = 0; j < 12; ++j) {
            ulonglong2 w = wrow[j];
            a0 = ffma2(fh[2 * j],     w.x, a0);
            a1 = ffma2(fh[2 * j + 1], w.y, a1);
        }
        float lo, hi; unpack2(add2(a0, a1), lo, hi);
        float ph = lo + hi;
        float full = ph + __shfl_xor_sync(0xFFFFFFFFu, ph, 1);
        float v = fmaxf(fmaf(full, sm->s5[o], sm->b5[o]), 0.0f);
        ss = fmaf(v, v, ss);
        const int rel = o - obase;
        if ((unsigned)rel < 48u) mybase[rel] = v;   // unnormalized, own half
    }

    const float rn = rsqrtf(ss);
    float4* o4 = (float4*)mybase;
#pragma unroll 3
    for (int i = 0; i < 12; ++i) {
        float4 v = o4[i];
        v.x *= rn; v.y *= rn; v.z *= rn; v.w *= rn;
        o4[i] = v;
    }
}

// ---------------------------------------------------------------------------
// launch
// ---------------------------------------------------------------------------
extern "C" void kernel_launch(void* const* d_in, const int* in_sizes, int n_in,
                              void* d_out, int out_size) {
    const float* x   = (const float*)d_in[0];
    const float* w1  = (const float*)d_in[1];
    const float* w2  = (const float*)d_in[2];
    const float* w3  = (const float*)d_in[3];
    const float* w4  = (const float*)d_in[4];
    const float* w5  = (const float*)d_in[5];
    const float* mw  = (const float*)d_in[6];
    const float* mb  = (const float*)d_in[7];
    const float* bn1 = (const float*)d_in[8];
    const float* bn2 = (const float*)d_in[9];
    const float* bn3 = (const float*)d_in[10];
    const float* bn4 = (const float*)d_in[11];
    const float* bn5 = (const float*)d_in[12];

    const size_t knn_smem  = NPTS * 12 + 3 * 64 * 17 * 8 + 256 * QCAP * 4; // ~89.5KB
    const size_t pool_smem = sizeof(SmemPool);            // ~38.8KB
    const size_t gemm_smem = sizeof(SmemGemm);            // ~37.6KB

    cudaFuncSetAttribute(knn_kernel,  cudaFuncAttributeMaxDynamicSharedMemorySize, (int)knn_smem);
    cudaFuncSetAttribute(pool_kernel, cudaFuncAttributeMaxDynamicSharedMemorySize, (int)pool_smem);
    cudaFuncSetAttribute(gemm_kernel, cudaFuncAttributeMaxDynamicSharedMemorySize, (int)gemm_smem);

    dim3 grid(NPTS / 64, BATCH);   // 64 x 8 = 512 blocks
    knn_kernel<<<grid, 256, knn_smem>>>(x);
    pool_kernel<<<grid, 256, pool_smem>>>(x, w1, w2, w3, w4, mw, mb,
                                          bn1, bn2, bn3, bn4);
    gemm_kernel<<<grid, 128, gemm_smem>>>(w5, bn5, (float*)d_out);
}

// round 16
// speedup vs baseline: 1.1415x; 1.1415x over previous
#include <cuda_runtime.h>
#include <cstdint>

#define NPTS  4096
#define BATCH 8
#define KNN_K 16

// scratch: neighbor indices (original within-batch indices), 2MB
__device__ int g_idx[BATCH * NPTS * KNN_K];
// scratch: pooled features, 96 floats per point packed as 48 u64, 12.6MB
__device__ __align__(16) unsigned long long g_feat[BATCH * NPTS * 48];

// ---------------------------------------------------------------------------
// packed f32x2 helpers
// ---------------------------------------------------------------------------
__device__ __forceinline__ unsigned long long ffma2(unsigned long long a,
                                                    unsigned long long b,
                                                    unsigned long long c) {
    unsigned long long d;
    asm("fma.rn.f32x2 %0, %1, %2, %3;" : "=l"(d) : "l"(a), "l"(b), "l"(c));
    return d;
}
__device__ __forceinline__ unsigned long long add2(unsigned long long a,
                                                   unsigned long long b) {
    unsigned long long d;
    asm("add.rn.f32x2 %0, %1, %2;" : "=l"(d) : "l"(a), "l"(b));
    return d;
}
__device__ __forceinline__ unsigned long long mul2(unsigned long long a,
                                                   unsigned long long b) {
    unsigned long long d;
    asm("mul.rn.f32x2 %0, %1, %2;" : "=l"(d) : "l"(a), "l"(b));
    return d;
}
__device__ __forceinline__ unsigned long long pack2(float lo, float hi) {
    unsigned long long p;
    asm("mov.b64 %0, {%1, %2};" : "=l"(p) : "f"(lo), "f"(hi));
    return p;
}
__device__ __forceinline__ void unpack2(unsigned long long p, float& lo, float& hi) {
    asm("mov.b64 {%0, %1}, %2;" : "=f"(lo), "=f"(hi) : "l"(p));
}

// sorted u64 lower-half bitonic merge: a (sorted asc) x b (sorted asc) -> a
__device__ __forceinline__ void merge16(unsigned long long* a,
                                        const unsigned long long* bsrc) {
    unsigned long long L[KNN_K];
#pragma unroll
    for (int i = 0; i < KNN_K; ++i) {
        unsigned long long bb = bsrc[KNN_K - 1 - i];
        L[i] = (a[i] < bb) ? a[i] : bb;
    }
#pragma unroll
    for (int j = 8; j >= 1; j >>= 1) {
#pragma unroll
        for (int i = 0; i < KNN_K; ++i) {
            if ((i & j) == 0) {
                unsigned long long lo = L[i], hi = L[i | j];
                unsigned long long mn = (lo < hi) ? lo : hi;
                unsigned long long mx = (lo < hi) ? hi : lo;
                L[i] = mn; L[i | j] = mx;
            }
        }
    }
#pragma unroll
    for (int i = 0; i < KNN_K; ++i) a[i] = L[i];
}

// ---------------------------------------------------------------------------
// Kernel 1: exact KNN, 4 threads/query (quarter ranges), buffered top-16.
// (byte-identical to the validated round-12 version)
// ---------------------------------------------------------------------------
#define QCAP 16   // per-lane FIFO capacity (u32 entries)

extern "C" __global__ void __launch_bounds__(256)
knn_kernel(const float* __restrict__ x) {
    extern __shared__ __align__(16) char smem_raw[];
    float2* sxy = (float2*)smem_raw;                                   // 32KB
    float*  ssq = (float*)(smem_raw + NPTS * 8);                       // 16KB
    unsigned long long* mbuf =
        (unsigned long long*)(smem_raw + NPTS * 12);                   // 3*64*17*8
    unsigned* qbuf = (unsigned*)(mbuf + 3 * 64 * 17);                  // 16KB

    const int tid = threadIdx.x;
    const int b   = blockIdx.y;
    const float2* __restrict__ xb = ((const float2*)x) + (size_t)b * NPTS;

    for (int i = tid; i < NPTS; i += 256) {
        float2 v = xb[i];
        sxy[i] = v;
        ssq[i] = __fadd_rn(__fmul_rn(v.x, v.x), __fmul_rn(v.y, v.y));
    }
    __syncthreads();

    const int qloc = tid & 63;
    const int part = tid >> 6;                    // warp-uniform (2 warps/part)
    const int q    = blockIdx.x * 64 + qloc;
    const float2 qv = sxy[q];
    const float qx = qv.x, qy = qv.y, qsq = ssq[q];

    // sentinel = mapped(+INF); unmaps to float +INF for the threshold
    unsigned bu[KNN_K];
    int      bi[KNN_K];
#pragma unroll
    for (int s = 0; s < KNN_K; ++s) { bu[s] = 0xFF800000u; bi[s] = 0; }

    const int jbeg = part * (NPTS / 4);
    int cnt = 0;
    float worstf = __int_as_float(0x7F800000);    // +INF

    auto insert = [&](unsigned u, int j) {
        bool c[KNN_K];
#pragma unroll
        for (int s = 0; s < KNN_K; ++s) c[s] = (u < bu[s]);
#pragma unroll
        for (int s = KNN_K - 1; s >= 1; --s) {
            bu[s] = c[s - 1] ? bu[s - 1] : (c[s] ? u : bu[s]);
            bi[s] = c[s - 1] ? bi[s - 1] : (c[s] ? j : bi[s]);
        }
        if (c[0]) { bu[0] = u; bi[0] = j; }
    };

    auto drain = [&]() {
#pragma unroll 1
        for (int t = 0; t < cnt; ++t) {           // divergent per-lane count
            int j = (int)qbuf[t * 256 + tid];
            float2 p = sxy[j];
            float ps = ssq[j];
            // exact reference formula, no FMA contraction
            float dot = __fadd_rn(__fmul_rn(qx, p.x), __fmul_rn(qy, p.y));
            float d   = __fsub_rn(__fadd_rn(qsq, ps), __fmul_rn(2.0f, dot));
            int ib = __float_as_int(d);
            unsigned u = (ib >= 0) ? ((unsigned)ib ^ 0x80000000u) : ~(unsigned)ib;
            if (u < bu[KNN_K - 1]) insert(u, j);
        }
        cnt = 0;
        // unmap bu[15] -> float threshold (sentinel -> +INF)
        unsigned u15 = bu[KNN_K - 1];
        int ib = (u15 & 0x80000000u) ? (int)(u15 ^ 0x80000000u) : (int)~u15;
        worstf = __int_as_float(ib);
    };

    const unsigned long long qx2 = pack2(qx, qx);
    const unsigned long long qy2 = pack2(qy, qy);
    const unsigned long long qs2 = pack2(qsq, qsq);
    const unsigned long long n22 = pack2(-2.0f, -2.0f);

#pragma unroll 1
    for (int blk = 0; blk < NPTS / 4; blk += 8) {
#pragma unroll
        for (int pp = 0; pp < 4; ++pp) {
            const int j = jbeg + blk + pp * 2;
            float4 pxy = *(const float4*)(sxy + j);        // x0,y0,x1,y1
            float2 ps  = *(const float2*)(ssq + j);
            unsigned long long px  = pack2(pxy.x, pxy.z);
            unsigned long long py  = pack2(pxy.y, pxy.w);
            unsigned long long psq = pack2(ps.x, ps.y);
            // per-half identical rounding to the scalar reference:
            unsigned long long dot = add2(mul2(qx2, px), mul2(qy2, py));
            unsigned long long dv  = add2(add2(qs2, psq), mul2(n22, dot));
            float d0, d1; unpack2(dv, d0, d1);
            if (d0 < worstf) { qbuf[cnt * 256 + tid] = (unsigned)j;       ++cnt; }
            if (d1 < worstf) { qbuf[cnt * 256 + tid] = (unsigned)(j + 1); ++cnt; }
        }
        if (__any_sync(0xFFFFFFFFu, cnt >= QCAP - 8)) drain();
    }
    drain();                                      // leftovers

    // parts 1..3 publish their sorted lists
    if (part != 0) {
        unsigned long long* dst = mbuf + ((part - 1) * 64 + qloc) * 17;
#pragma unroll
        for (int s = 0; s < KNN_K; ++s)
            dst[s] = ((unsigned long long)bu[s] << 32) | (unsigned)bi[s];
    }
    __syncthreads();

    if (part == 0) {
        unsigned long long L[KNN_K];
#pragma unroll
        for (int s = 0; s < KNN_K; ++s)
            L[s] = ((unsigned long long)bu[s] << 32) | (unsigned)bi[s];

        merge16(L, mbuf + (0 * 64 + qloc) * 17);
        unsigned long long M[KNN_K];
        const unsigned long long* p2 = mbuf + (1 * 64 + qloc) * 17;
#pragma unroll
        for (int s = 0; s < KNN_K; ++s) M[s] = p2[s];
        merge16(M, mbuf + (2 * 64 + qloc) * 17);
        merge16(L, M);

        int* outp = g_idx + ((size_t)b * NPTS + q) * KNN_K;
#pragma unroll
        for (int s = 0; s < KNN_K; ++s)
            outp[s] = (int)(L[s] & 0xFFFFFFFFu);
    }
}

// ---------------------------------------------------------------------------
// Kernel 2a: pooling, round-12 2-way feature split (part0 = pools + L4
// outputs 0..31 -> u64 [0..32); part1 = L4 outputs 32..63 -> u64 [32..48)),
// but with the layer-4 loop FULLY UNROLLED via template<int PART> so every
// facc index is a compile-time constant -> facc stays in registers (the
// round-12 runtime fi forced facc into local memory). NO launch_bounds cap
// (the round-15 128-reg cap caused the spill storm). 128 threads/block.
// Accumulation order per feature unchanged -> bit-identical g_feat.
// ---------------------------------------------------------------------------
struct __align__(16) SmemPool {
    float2 pts[NPTS];          // 32KB
    float w1[32];              // [8][4]
    float w2[64];              // [8][8]
    float w3[128];             // [16][8]
    float w4[1024];            // [64][16]
    float mw[64];              // [4][16]
    float mb[4];
    float s1[8],  b1[8];
    float s2[8],  b2[8];
    float s3[16], b3[16];
    float s4[64], b4[64];
};

template<int PART>
__device__ __forceinline__ void pool_body(const SmemPool* sm,
                                          const int* __restrict__ gi,
                                          float2 ctr, int gq) {
    constexpr int OBEG  = (PART == 0) ? 0 : 32;          // L4 output start
    constexpr int POOLN = (PART == 0) ? 16 : 0;          // pooled u64 slots
    constexpr int NF    = POOLN + 16;                    // 32 or 16 u64

    unsigned long long facc[NF];
#pragma unroll
    for (int i = 0; i < NF; ++i) facc[i] = 0ULL;

#pragma unroll 1
    for (int k = 0; k < KNN_K; ++k) {
        const int nbk = gi[k];
        const float2 P = sm->pts[nbk];
        const unsigned long long m3p = pack2(sm->mw[32 + k], sm->mw[32 + k]);
        const unsigned long long m4p = pack2(sm->mw[48 + k], sm->mw[48 + k]);

        // layer 1: 4 -> 8
        float h1[8];
#pragma unroll
        for (int o = 0; o < 8; o += 2) {
#pragma unroll
            for (int t = 0; t < 2; ++t) {
                float4 w = *(const float4*)(sm->w1 + (o + t) * 4);
                float v = P.x * w.x + P.y * w.y + ctr.x * w.z + ctr.y * w.w;
                h1[o + t] = fmaxf(fmaf(v, sm->s1[o + t], sm->b1[o + t]), 0.0f);
            }
            if (PART == 0) {
                const unsigned long long m1p = pack2(sm->mw[k], sm->mw[k]);
                facc[o / 2] = ffma2(pack2(h1[o], h1[o + 1]), m1p, facc[o / 2]);
            }
        }
        // layer 2: 8 -> 8
        float h2[8];
#pragma unroll
        for (int o = 0; o < 8; o += 2) {
#pragma unroll
            for (int t = 0; t < 2; ++t) {
                const float4* w = (const float4*)(sm->w2 + (o + t) * 8);
                float4 wa = w[0], wb = w[1];
                float v = h1[0] * wa.x + h1[1] * wa.y + h1[2] * wa.z + h1[3] * wa.w
                        + h1[4] * wb.x + h1[5] * wb.y + h1[6] * wb.z + h1[7] * wb.w;
                h2[o + t] = fmaxf(fmaf(v, sm->s2[o + t], sm->b2[o + t]), 0.0f);
            }
            if (PART == 0) {
                const unsigned long long m2p = pack2(sm->mw[16 + k], sm->mw[16 + k]);
                facc[4 + o / 2] = ffma2(pack2(h2[o], h2[o + 1]), m2p, facc[4 + o / 2]);
            }
        }
        // layer 3: 8 -> 16 (packed pairs for layer-4 dots)
        unsigned long long h3p[8];
#pragma unroll
        for (int o = 0; o < 16; o += 2) {
            float vv[2];
#pragma unroll
            for (int t = 0; t < 2; ++t) {
                const float4* w = (const float4*)(sm->w3 + (o + t) * 8);
                float4 wa = w[0], wb = w[1];
                float v = h2[0] * wa.x + h2[1] * wa.y + h2[2] * wa.z + h2[3] * wa.w
                        + h2[4] * wb.x + h2[5] * wb.y + h2[6] * wb.z + h2[7] * wb.w;
                vv[t] = fmaxf(fmaf(v, sm->s3[o + t], sm->b3[o + t]), 0.0f);
            }
            h3p[o / 2] = pack2(vv[0], vv[1]);
            if (PART == 0)
                facc[8 + o / 2] = ffma2(h3p[o / 2], m3p, facc[8 + o / 2]);
        }
        // layer 4: 16 pairs, FULLY UNROLLED -> static facc indices
#pragma unroll
        for (int pp = 0; pp < 16; ++pp) {
            const int o = OBEG + pp * 2;
            float vv[2];
#pragma unroll
            for (int t = 0; t < 2; ++t) {
                const ulonglong2* wrow = (const ulonglong2*)(sm->w4 + (o + t) * 16);
                ulonglong2 wa = wrow[0], wb = wrow[1], wc = wrow[2], wd = wrow[3];
                unsigned long long acc = ffma2(h3p[0], wa.x, 0ULL);
                acc = ffma2(h3p[1], wa.y, acc);
                acc = ffma2(h3p[2], wb.x, acc);
                acc = ffma2(h3p[3], wb.y, acc);
                acc = ffma2(h3p[4], wc.x, acc);
                acc = ffma2(h3p[5], wc.y, acc);
                acc = ffma2(h3p[6], wd.x, acc);
                acc = ffma2(h3p[7], wd.y, acc);
                float lo, hi; unpack2(acc, lo, hi);
                float v = lo + hi;
                vv[t] = fmaxf(fmaf(v, sm->s4[o + t], sm->b4[o + t]), 0.0f);
            }
            facc[POOLN + pp] = ffma2(pack2(vv[0], vv[1]), m4p, facc[POOLN + pp]);
        }
    }

    // mlp biases (static per part)
    {
        const unsigned long long c3 = pack2(sm->mb[3], sm->mb[3]);
        if (PART == 0) {
            const unsigned long long c0 = pack2(sm->mb[0], sm->mb[0]);
            const unsigned long long c1 = pack2(sm->mb[1], sm->mb[1]);
            const unsigned long long c2 = pack2(sm->mb[2], sm->mb[2]);
#pragma unroll
            for (int i = 0; i < 4; ++i)  facc[i]      = add2(facc[i], c0);
#pragma unroll
            for (int i = 0; i < 4; ++i)  facc[4 + i]  = add2(facc[4 + i], c1);
#pragma unroll
            for (int i = 0; i < 8; ++i)  facc[8 + i]  = add2(facc[8 + i], c2);
#pragma unroll
            for (int i = 0; i < 16; ++i) facc[16 + i] = add2(facc[16 + i], c3);
        } else {
#pragma unroll
            for (int i = 0; i < 16; ++i) facc[i] = add2(facc[i], c3);
        }
    }

    constexpr int OFF = (PART == 0) ? 0 : 32;            // u64 offset in row
    ulonglong2* dst = (ulonglong2*)(g_feat + (size_t)gq * 48 + OFF);
#pragma unroll
    for (int i = 0; i < NF / 2; ++i)
        dst[i] = make_ulonglong2(facc[2 * i], facc[2 * i + 1]);
}

extern "C" __global__ void __launch_bounds__(128)
pool_kernel(const float* __restrict__ x,
            const float* __restrict__ w1, const float* __restrict__ w2,
            const float* __restrict__ w3, const float* __restrict__ w4,
            const float* __restrict__ mw, const float* __restrict__ mb,
            const float* __restrict__ bn1, const float* __restrict__ bn2,
            const float* __restrict__ bn3, const float* __restrict__ bn4) {
    extern __shared__ __align__(16) char smem_raw[];
    SmemPool* sm = (SmemPool*)smem_raw;

    const int tid = threadIdx.x;
    const int b   = blockIdx.y;

    for (int i = tid; i < NPTS; i += 128) sm->pts[i] = ((const float2*)x)[(size_t)b * NPTS + i];
    for (int i = tid; i < 32;   i += 128) sm->w1[i] = w1[i];
    for (int i = tid; i < 64;   i += 128) sm->w2[i] = w2[i];
    for (int i = tid; i < 128;  i += 128) sm->w3[i] = w3[i];
    for (int i = tid; i < 1024; i += 128) sm->w4[i] = w4[i];
    for (int i = tid; i < 64;   i += 128) sm->mw[i] = mw[i];
    if (tid < 4) sm->mb[tid] = mb[tid];
    for (int i = tid; i < 8;  i += 128) {
        float s = bn1[i] * rsqrtf(bn1[24 + i] + 1e-5f);
        sm->s1[i] = s; sm->b1[i] = bn1[8 + i] - bn1[16 + i] * s;
        float t = bn2[i] * rsqrtf(bn2[24 + i] + 1e-5f);
        sm->s2[i] = t; sm->b2[i] = bn2[8 + i] - bn2[16 + i] * t;
    }
    for (int i = tid; i < 16; i += 128) {
        float s = bn3[i] * rsqrtf(bn3[48 + i] + 1e-5f);
        sm->s3[i] = s; sm->b3[i] = bn3[16 + i] - bn3[32 + i] * s;
    }
    for (int i = tid; i < 64; i += 128) {
        float s = bn4[i] * rsqrtf(bn4[192 + i] + 1e-5f);
        sm->s4[i] = s; sm->b4[i] = bn4[64 + i] - bn4[128 + i] * s;
    }
    __syncthreads();

    const int nloc = tid & 63;
    const int part = tid >> 6;                    // warp-uniform
    const int n    = blockIdx.x * 64 + nloc;
    const int gq   = b * NPTS + n;
    const int* __restrict__ gi = g_idx + (size_t)gq * KNN_K;
    const float2 ctr = sm->pts[n];

    if (part == 0) pool_body<0>(sm, gi, ctr, gq);
    else           pool_body<1>(sm, gi, ctr, gq);
}

// ---------------------------------------------------------------------------
// Kernel 2b: final 96x96 GEMM + BN/ReLU + L2 normalize
// (byte-identical to rounds 6-12)
// ---------------------------------------------------------------------------
struct __align__(16) SmemGemm {
    float w5[9216];            // [96][96]
    float s5[96], b5[96];
};

extern "C" __global__ void __launch_bounds__(128)
gemm_kernel(const float* __restrict__ w5, const float* __restrict__ bn5,
            float* __restrict__ out) {
    extern __shared__ __align__(16) char smem_raw[];
    SmemGemm* sm = (SmemGemm*)smem_raw;

    const int tid = threadIdx.x;
    const int b   = blockIdx.y;

    for (int i = tid; i < 9216; i += 128) sm->w5[i] = w5[i];
    for (int i = tid; i < 96; i += 128) {
        float s = bn5[i] * rsqrtf(bn5[288 + i] + 1e-5f);
        sm->s5[i] = s; sm->b5[i] = bn5[96 + i] - bn5[192 + i] * s;
    }
    __syncthreads();

    const int half = tid & 1;
    const int n    = blockIdx.x * 64 + (tid >> 1);
    const int gq   = b * NPTS + n;

    unsigned long long fh[24];
    const ulonglong2* fsrc = (const ulonglong2*)(g_feat + (size_t)gq * 48 + half * 24);
#pragma unroll
    for (int i = 0; i < 12; ++i) {
        ulonglong2 t = fsrc[i];
        fh[2 * i] = t.x; fh[2 * i + 1] = t.y;
    }

    const int obase = half * 48;
    float* __restrict__ mybase = out + (size_t)gq * 96 + obase;
    float ss = 0.0f;

#pragma unroll 1
    for (int o = 0; o < 96; ++o) {
        const ulonglong2* wrow = (const ulonglong2*)(sm->w5 + o * 96 + half * 48);
        unsigned long long a0 = 0ULL, a1 = 0ULL;
#pragma unroll
        for (int j = 0; j < 12; ++j) {
            ulonglong2 w = wrow[j];
            a0 = ffma2(fh[2 * j],     w.x, a0);
            a1 = ffma2(fh[2 * j + 1], w.y, a1);
        }
        float lo, hi; unpack2(add2(a0, a1), lo, hi);
        float ph = lo + hi;
        float full = ph + __shfl_xor_sync(0xFFFFFFFFu, ph, 1);
        float v = fmaxf(fmaf(full, sm->s5[o], sm->b5[o]), 0.0f);
        ss = fmaf(v, v, ss);
        const int rel = o - obase;
        if ((unsigned)rel < 48u) mybase[rel] = v;   // unnormalized, own half
    }

    const float rn = rsqrtf(ss);
    float4* o4 = (float4*)mybase;
#pragma unroll 3
    for (int i = 0; i < 12; ++i) {
        float4 v = o4[i];
        v.x *= rn; v.y *= rn; v.z *= rn; v.w *= rn;
        o4[i] = v;
    }
}

// ---------------------------------------------------------------------------
// launch
// ---------------------------------------------------------------------------
extern "C" void kernel_launch(void* const* d_in, const int* in_sizes, int n_in,
                              void* d_out, int out_size) {
    const float* x   = (const float*)d_in[0];
    const float* w1  = (const float*)d_in[1];
    const float* w2  = (const float*)d_in[2];
    const float* w3  = (const float*)d_in[3];
    const float* w4  = (const float*)d_in[4];
    const float* w5  = (const float*)d_in[5];
    const float* mw  = (const float*)d_in[6];
    const float* mb  = (const float*)d_in[7];
    const float* bn1 = (const float*)d_in[8];
    const float* bn2 = (const float*)d_in[9];
    const float* bn3 = (const float*)d_in[10];
    const float* bn4 = (const float*)d_in[11];
    const float* bn5 = (const float*)d_in[12];

    const size_t knn_smem  = NPTS * 12 + 3 * 64 * 17 * 8 + 256 * QCAP * 4; // ~89.5KB
    const size_t pool_smem = sizeof(SmemPool);            // ~38.8KB
    const size_t gemm_smem = sizeof(SmemGemm);            // ~37.6KB

    cudaFuncSetAttribute(knn_kernel,  cudaFuncAttributeMaxDynamicSharedMemorySize, (int)knn_smem);
    cudaFuncSetAttribute(pool_kernel, cudaFuncAttributeMaxDynamicSharedMemorySize, (int)pool_smem);
    cudaFuncSetAttribute(gemm_kernel, cudaFuncAttributeMaxDynamicSharedMemorySize, (int)gemm_smem);

    dim3 grid(NPTS / 64, BATCH);   // 64 x 8 = 512 blocks
    knn_kernel<<<grid, 256, knn_smem>>>(x);
    pool_kernel<<<grid, 128, pool_smem>>>(x, w1, w2, w3, w4, mw, mb,
                                          bn1, bn2, bn3, bn4);
    gemm_kernel<<<grid, 128, gemm_smem>>>(w5, bn5, (float*)d_out);
}

// round 17
// speedup vs baseline: 2.8744x; 2.5180x over previous
#include <cuda_runtime.h>
#include <cstdint>

#define NPTS  4096
#define BATCH 8
#define KNN_K 16

// scratch: neighbor indices (original within-batch indices), 2MB
__device__ int g_idx[BATCH * NPTS * KNN_K];
// scratch: pooled features, 96 floats per point packed as 48 u64, 12.6MB
__device__ __align__(16) unsigned long long g_feat[BATCH * NPTS * 48];

// ---------------------------------------------------------------------------
// packed f32x2 helpers
// ---------------------------------------------------------------------------
__device__ __forceinline__ unsigned long long ffma2(unsigned long long a,
                                                    unsigned long long b,
                                                    unsigned long long c) {
    unsigned long long d;
    asm("fma.rn.f32x2 %0, %1, %2, %3;" : "=l"(d) : "l"(a), "l"(b), "l"(c));
    return d;
}
__device__ __forceinline__ unsigned long long add2(unsigned long long a,
                                                   unsigned long long b) {
    unsigned long long d;
    asm("add.rn.f32x2 %0, %1, %2;" : "=l"(d) : "l"(a), "l"(b));
    return d;
}
__device__ __forceinline__ unsigned long long mul2(unsigned long long a,
                                                   unsigned long long b) {
    unsigned long long d;
    asm("mul.rn.f32x2 %0, %1, %2;" : "=l"(d) : "l"(a), "l"(b));
    return d;
}
__device__ __forceinline__ unsigned long long pack2(float lo, float hi) {
    unsigned long long p;
    asm("mov.b64 %0, {%1, %2};" : "=l"(p) : "f"(lo), "f"(hi));
    return p;
}
__device__ __forceinline__ void unpack2(unsigned long long p, float& lo, float& hi) {
    asm("mov.b64 {%0, %1}, %2;" : "=f"(lo), "=f"(hi) : "l"(p));
}

// sorted u64 lower-half bitonic merge: a (sorted asc) x b (sorted asc) -> a
__device__ __forceinline__ void merge16(unsigned long long* a,
                                        const unsigned long long* bsrc) {
    unsigned long long L[KNN_K];
#pragma unroll
    for (int i = 0; i < KNN_K; ++i) {
        unsigned long long bb = bsrc[KNN_K - 1 - i];
        L[i] = (a[i] < bb) ? a[i] : bb;
    }
#pragma unroll
    for (int j = 8; j >= 1; j >>= 1) {
#pragma unroll
        for (int i = 0; i < KNN_K; ++i) {
            if ((i & j) == 0) {
                unsigned long long lo = L[i], hi = L[i | j];
                unsigned long long mn = (lo < hi) ? lo : hi;
                unsigned long long mx = (lo < hi) ? hi : lo;
                L[i] = mn; L[i | j] = mx;
            }
        }
    }
#pragma unroll
    for (int i = 0; i < KNN_K; ++i) a[i] = L[i];
}

// ---------------------------------------------------------------------------
// Kernel 1: exact KNN, 4 threads/query (quarter ranges), buffered top-16.
// (byte-identical to the validated round-12 version)
// ---------------------------------------------------------------------------
#define QCAP 16   // per-lane FIFO capacity (u32 entries)

extern "C" __global__ void __launch_bounds__(256)
knn_kernel(const float* __restrict__ x) {
    extern __shared__ __align__(16) char smem_raw[];
    float2* sxy = (float2*)smem_raw;                                   // 32KB
    float*  ssq = (float*)(smem_raw + NPTS * 8);                       // 16KB
    unsigned long long* mbuf =
        (unsigned long long*)(smem_raw + NPTS * 12);                   // 3*64*17*8
    unsigned* qbuf = (unsigned*)(mbuf + 3 * 64 * 17);                  // 16KB

    const int tid = threadIdx.x;
    const int b   = blockIdx.y;
    const float2* __restrict__ xb = ((const float2*)x) + (size_t)b * NPTS;

    for (int i = tid; i < NPTS; i += 256) {
        float2 v = xb[i];
        sxy[i] = v;
        ssq[i] = __fadd_rn(__fmul_rn(v.x, v.x), __fmul_rn(v.y, v.y));
    }
    __syncthreads();

    const int qloc = tid & 63;
    const int part = tid >> 6;                    // warp-uniform (2 warps/part)
    const int q    = blockIdx.x * 64 + qloc;
    const float2 qv = sxy[q];
    const float qx = qv.x, qy = qv.y, qsq = ssq[q];

    // sentinel = mapped(+INF); unmaps to float +INF for the threshold
    unsigned bu[KNN_K];
    int      bi[KNN_K];
#pragma unroll
    for (int s = 0; s < KNN_K; ++s) { bu[s] = 0xFF800000u; bi[s] = 0; }

    const int jbeg = part * (NPTS / 4);
    int cnt = 0;
    float worstf = __int_as_float(0x7F800000);    // +INF

    auto insert = [&](unsigned u, int j) {
        bool c[KNN_K];
#pragma unroll
        for (int s = 0; s < KNN_K; ++s) c[s] = (u < bu[s]);
#pragma unroll
        for (int s = KNN_K - 1; s >= 1; --s) {
            bu[s] = c[s - 1] ? bu[s - 1] : (c[s] ? u : bu[s]);
            bi[s] = c[s - 1] ? bi[s - 1] : (c[s] ? j : bi[s]);
        }
        if (c[0]) { bu[0] = u; bi[0] = j; }
    };

    auto drain = [&]() {
#pragma unroll 1
        for (int t = 0; t < cnt; ++t) {           // divergent per-lane count
            int j = (int)qbuf[t * 256 + tid];
            float2 p = sxy[j];
            float ps = ssq[j];
            // exact reference formula, no FMA contraction
            float dot = __fadd_rn(__fmul_rn(qx, p.x), __fmul_rn(qy, p.y));
            float d   = __fsub_rn(__fadd_rn(qsq, ps), __fmul_rn(2.0f, dot));
            int ib = __float_as_int(d);
            unsigned u = (ib >= 0) ? ((unsigned)ib ^ 0x80000000u) : ~(unsigned)ib;
            if (u < bu[KNN_K - 1]) insert(u, j);
        }
        cnt = 0;
        // unmap bu[15] -> float threshold (sentinel -> +INF)
        unsigned u15 = bu[KNN_K - 1];
        int ib = (u15 & 0x80000000u) ? (int)(u15 ^ 0x80000000u) : (int)~u15;
        worstf = __int_as_float(ib);
    };

    const unsigned long long qx2 = pack2(qx, qx);
    const unsigned long long qy2 = pack2(qy, qy);
    const unsigned long long qs2 = pack2(qsq, qsq);
    const unsigned long long n22 = pack2(-2.0f, -2.0f);

#pragma unroll 1
    for (int blk = 0; blk < NPTS / 4; blk += 8) {
#pragma unroll
        for (int pp = 0; pp < 4; ++pp) {
            const int j = jbeg + blk + pp * 2;
            float4 pxy = *(const float4*)(sxy + j);        // x0,y0,x1,y1
            float2 ps  = *(const float2*)(ssq + j);
            unsigned long long px  = pack2(pxy.x, pxy.z);
            unsigned long long py  = pack2(pxy.y, pxy.w);
            unsigned long long psq = pack2(ps.x, ps.y);
            // per-half identical rounding to the scalar reference:
            unsigned long long dot = add2(mul2(qx2, px), mul2(qy2, py));
            unsigned long long dv  = add2(add2(qs2, psq), mul2(n22, dot));
            float d0, d1; unpack2(dv, d0, d1);
            if (d0 < worstf) { qbuf[cnt * 256 + tid] = (unsigned)j;       ++cnt; }
            if (d1 < worstf) { qbuf[cnt * 256 + tid] = (unsigned)(j + 1); ++cnt; }
        }
        if (__any_sync(0xFFFFFFFFu, cnt >= QCAP - 8)) drain();
    }
    drain();                                      // leftovers

    // parts 1..3 publish their sorted lists
    if (part != 0) {
        unsigned long long* dst = mbuf + ((part - 1) * 64 + qloc) * 17;
#pragma unroll
        for (int s = 0; s < KNN_K; ++s)
            dst[s] = ((unsigned long long)bu[s] << 32) | (unsigned)bi[s];
    }
    __syncthreads();

    if (part == 0) {
        unsigned long long L[KNN_K];
#pragma unroll
        for (int s = 0; s < KNN_K; ++s)
            L[s] = ((unsigned long long)bu[s] << 32) | (unsigned)bi[s];

        merge16(L, mbuf + (0 * 64 + qloc) * 17);
        unsigned long long M[KNN_K];
        const unsigned long long* p2 = mbuf + (1 * 64 + qloc) * 17;
#pragma unroll
        for (int s = 0; s < KNN_K; ++s) M[s] = p2[s];
        merge16(M, mbuf + (2 * 64 + qloc) * 17);
        merge16(L, M);

        int* outp = g_idx + ((size_t)b * NPTS + q) * KNN_K;
#pragma unroll
        for (int s = 0; s < KNN_K; ++s)
            outp[s] = (int)(L[s] & 0xFFFFFFFFu);
    }
}

// ---------------------------------------------------------------------------
// Kernel 2a: pooling (layers 1-4 over 16 neighbors), REBALANCED feature-split:
// part 0 -> features [0..64)  (layer1/2/3 pools + layer4 outputs 0..31)
// part 1 -> features [64..96) (layer4 outputs 32..63)
// (byte-identical to round 12 — the 341.5us best; two attempted "fixes"
//  of its dynamic facc indexing both spilled catastrophically. Leave it.)
// ---------------------------------------------------------------------------
struct __align__(16) SmemPool {
    float2 pts[NPTS];          // 32KB
    float w1[32];              // [8][4]
    float w2[64];              // [8][8]
    float w3[128];             // [16][8]
    float w4[1024];            // [64][16]
    float mw[64];              // [4][16]
    float mb[4];
    float s1[8],  b1[8];
    float s2[8],  b2[8];
    float s3[16], b3[16];
    float s4[64], b4[64];
};

extern "C" __global__ void __launch_bounds__(128)
pool_kernel(const float* __restrict__ x,
            const float* __restrict__ w1, const float* __restrict__ w2,
            const float* __restrict__ w3, const float* __restrict__ w4,
            const float* __restrict__ mw, const float* __restrict__ mb,
            const float* __restrict__ bn1, const float* __restrict__ bn2,
            const float* __restrict__ bn3, const float* __restrict__ bn4) {
    extern __shared__ __align__(16) char smem_raw[];
    SmemPool* sm = (SmemPool*)smem_raw;

    const int tid = threadIdx.x;
    const int b   = blockIdx.y;

    for (int i = tid; i < NPTS; i += 128) sm->pts[i] = ((const float2*)x)[(size_t)b * NPTS + i];
    for (int i = tid; i < 32;   i += 128) sm->w1[i] = w1[i];
    for (int i = tid; i < 64;   i += 128) sm->w2[i] = w2[i];
    for (int i = tid; i < 128;  i += 128) sm->w3[i] = w3[i];
    for (int i = tid; i < 1024; i += 128) sm->w4[i] = w4[i];
    for (int i = tid; i < 64;   i += 128) sm->mw[i] = mw[i];
    if (tid < 4) sm->mb[tid] = mb[tid];
    for (int i = tid; i < 8;  i += 128) {
        float s = bn1[i] * rsqrtf(bn1[24 + i] + 1e-5f);
        sm->s1[i] = s; sm->b1[i] = bn1[8 + i] - bn1[16 + i] * s;
        float t = bn2[i] * rsqrtf(bn2[24 + i] + 1e-5f);
        sm->s2[i] = t; sm->b2[i] = bn2[8 + i] - bn2[16 + i] * t;
    }
    for (int i = tid; i < 16; i += 128) {
        float s = bn3[i] * rsqrtf(bn3[48 + i] + 1e-5f);
        sm->s3[i] = s; sm->b3[i] = bn3[16 + i] - bn3[32 + i] * s;
    }
    for (int i = tid; i < 64; i += 128) {
        float s = bn4[i] * rsqrtf(bn4[192 + i] + 1e-5f);
        sm->s4[i] = s; sm->b4[i] = bn4[64 + i] - bn4[128 + i] * s;
    }
    __syncthreads();

    const int nloc = tid & 63;
    const int part = tid >> 6;                    // warp-uniform
    const int n    = blockIdx.x * 64 + nloc;
    const int gq   = b * NPTS + n;
    const int* __restrict__ gi = g_idx + (size_t)gq * KNN_K;

    // part0: facc[0..32) = features [0..64); part1: facc[0..16) = features [64..96)
    unsigned long long facc[32];
#pragma unroll
    for (int i = 0; i < 32; ++i) facc[i] = 0ULL;

    const float2 ctr = sm->pts[n];
    const int obeg = part ? 32 : 0;
    const int oend = part ? 64 : 32;

#pragma unroll 1
    for (int k = 0; k < KNN_K; ++k) {
        const int nbk = gi[k];
        const float2 P = sm->pts[nbk];
        const unsigned long long m1p = pack2(sm->mw[k],      sm->mw[k]);
        const unsigned long long m2p = pack2(sm->mw[16 + k], sm->mw[16 + k]);
        const unsigned long long m3p = pack2(sm->mw[32 + k], sm->mw[32 + k]);
        const unsigned long long m4p = pack2(sm->mw[48 + k], sm->mw[48 + k]);

        // layer 1: 4 -> 8
        float h1[8];
#pragma unroll
        for (int o = 0; o < 8; o += 2) {
#pragma unroll
            for (int t = 0; t < 2; ++t) {
                float4 w = *(const float4*)(sm->w1 + (o + t) * 4);
                float v = P.x * w.x + P.y * w.y + ctr.x * w.z + ctr.y * w.w;
                h1[o + t] = fmaxf(fmaf(v, sm->s1[o + t], sm->b1[o + t]), 0.0f);
            }
            if (part == 0)
                facc[o / 2] = ffma2(pack2(h1[o], h1[o + 1]), m1p, facc[o / 2]);
        }
        // layer 2: 8 -> 8
        float h2[8];
#pragma unroll
        for (int o = 0; o < 8; o += 2) {
#pragma unroll
            for (int t = 0; t < 2; ++t) {
                const float4* w = (const float4*)(sm->w2 + (o + t) * 8);
                float4 wa = w[0], wb = w[1];
                float v = h1[0] * wa.x + h1[1] * wa.y + h1[2] * wa.z + h1[3] * wa.w
                        + h1[4] * wb.x + h1[5] * wb.y + h1[6] * wb.z + h1[7] * wb.w;
                h2[o + t] = fmaxf(fmaf(v, sm->s2[o + t], sm->b2[o + t]), 0.0f);
            }
            if (part == 0)
                facc[4 + o / 2] = ffma2(pack2(h2[o], h2[o + 1]), m2p, facc[4 + o / 2]);
        }
        // layer 3: 8 -> 16 (packed pairs for layer-4 dots)
        unsigned long long h3p[8];
#pragma unroll
        for (int o = 0; o < 16; o += 2) {
            float vv[2];
#pragma unroll
            for (int t = 0; t < 2; ++t) {
                const float4* w = (const float4*)(sm->w3 + (o + t) * 8);
                float4 wa = w[0], wb = w[1];
                float v = h2[0] * wa.x + h2[1] * wa.y + h2[2] * wa.z + h2[3] * wa.w
                        + h2[4] * wb.x + h2[5] * wb.y + h2[6] * wb.z + h2[7] * wb.w;
                vv[t] = fmaxf(fmaf(v, sm->s3[o + t], sm->b3[o + t]), 0.0f);
            }
            h3p[o / 2] = pack2(vv[0], vv[1]);
            if (part == 0)
                facc[8 + o / 2] = ffma2(h3p[o / 2], m3p, facc[8 + o / 2]);
        }
        // layer 4: this part's output range
#pragma unroll 1
        for (int o = obeg; o < oend; o += 2) {
            float vv[2];
#pragma unroll
            for (int t = 0; t < 2; ++t) {
                const ulonglong2* wrow = (const ulonglong2*)(sm->w4 + (o + t) * 16);
                ulonglong2 wa = wrow[0], wb = wrow[1], wc = wrow[2], wd = wrow[3];
                unsigned long long acc = ffma2(h3p[0], wa.x, 0ULL);
                acc = ffma2(h3p[1], wa.y, acc);
                acc = ffma2(h3p[2], wb.x, acc);
                acc = ffma2(h3p[3], wb.y, acc);
                acc = ffma2(h3p[4], wc.x, acc);
                acc = ffma2(h3p[5], wc.y, acc);
                acc = ffma2(h3p[6], wd.x, acc);
                acc = ffma2(h3p[7], wd.y, acc);
                float lo, hi; unpack2(acc, lo, hi);
                float v = lo + hi;
                vv[t] = fmaxf(fmaf(v, sm->s4[o + t], sm->b4[o + t]), 0.0f);
            }
            const int fi = (part ? (o - 32) : (o + 32)) >> 1;
            facc[fi] = ffma2(pack2(vv[0], vv[1]), m4p, facc[fi]);
        }
    }

    // mlp biases
    {
        const unsigned long long c3 = pack2(sm->mb[3], sm->mb[3]);
        if (part == 0) {
            const unsigned long long c0 = pack2(sm->mb[0], sm->mb[0]);
            const unsigned long long c1 = pack2(sm->mb[1], sm->mb[1]);
            const unsigned long long c2 = pack2(sm->mb[2], sm->mb[2]);
#pragma unroll
            for (int i = 0; i < 4; ++i)  facc[i]      = add2(facc[i], c0);
#pragma unroll
            for (int i = 0; i < 4; ++i)  facc[4 + i]  = add2(facc[4 + i], c1);
#pragma unroll
            for (int i = 0; i < 8; ++i)  facc[8 + i]  = add2(facc[8 + i], c2);
#pragma unroll
            for (int i = 0; i < 16; ++i) facc[16 + i] = add2(facc[16 + i], c3);
        } else {
#pragma unroll
            for (int i = 0; i < 16; ++i) facc[i] = add2(facc[i], c3);
        }
    }

    // part0 writes u64 [0..32) of g_feat row; part1 writes [32..48)
    if (part == 0) {
        ulonglong2* dst = (ulonglong2*)(g_feat + (size_t)gq * 48);
#pragma unroll
        for (int i = 0; i < 16; ++i)
            dst[i] = make_ulonglong2(facc[2 * i], facc[2 * i + 1]);
    } else {
        ulonglong2* dst = (ulonglong2*)(g_feat + (size_t)gq * 48 + 32);
#pragma unroll
        for (int i = 0; i < 8; ++i)
            dst[i] = make_ulonglong2(facc[2 * i], facc[2 * i + 1]);
    }
}

// ---------------------------------------------------------------------------
// Kernel 2b: final 96x96 GEMM + BN/ReLU + L2 normalize.
// NEW: 4 threads per point (k split 4 ways, 24 values each), 2-level
// shfl_xor butterfly to form the full dot. Reduction order change is pure
// fp32 reassociation (~1e-7), far below the 1e-3 gate.
// ---------------------------------------------------------------------------
struct __align__(16) SmemGemm {
    float w5[9216];            // [96][96]
    float s5[96], b5[96];
};

extern "C" __global__ void __launch_bounds__(256)
gemm_kernel(const float* __restrict__ w5, const float* __restrict__ bn5,
            float* __restrict__ out) {
    extern __shared__ __align__(16) char smem_raw[];
    SmemGemm* sm = (SmemGemm*)smem_raw;

    const int tid = threadIdx.x;
    const int b   = blockIdx.y;

    for (int i = tid; i < 9216; i += 256) sm->w5[i] = w5[i];
    for (int i = tid; i < 96; i += 256) {
        float s = bn5[i] * rsqrtf(bn5[288 + i] + 1e-5f);
        sm->s5[i] = s; sm->b5[i] = bn5[96 + i] - bn5[192 + i] * s;
    }
    __syncthreads();

    const int quarter = tid & 3;
    const int n       = blockIdx.x * 64 + (tid >> 2);
    const int gq      = b * NPTS + n;

    // this quarter's 24 k-values (12 u64)
    unsigned long long fh[12];
    const ulonglong2* fsrc = (const ulonglong2*)(g_feat + (size_t)gq * 48 + quarter * 12);
#pragma unroll
    for (int i = 0; i < 6; ++i) {
        ulonglong2 t = fsrc[i];
        fh[2 * i] = t.x; fh[2 * i + 1] = t.y;
    }

    const int obase = quarter * 24;
    float* __restrict__ mybase = out + (size_t)gq * 96 + obase;
    float ss = 0.0f;

#pragma unroll 1
    for (int o = 0; o < 96; ++o) {
        const ulonglong2* wrow = (const ulonglong2*)(sm->w5 + o * 96 + quarter * 24);
        unsigned long long a0 = 0ULL, a1 = 0ULL;
#pragma unroll
        for (int j = 0; j < 6; ++j) {
            ulonglong2 w = wrow[j];
            a0 = ffma2(fh[2 * j],     w.x, a0);
            a1 = ffma2(fh[2 * j + 1], w.y, a1);
        }
        float lo, hi; unpack2(add2(a0, a1), lo, hi);
        float ph = lo + hi;
        float s1 = ph + __shfl_xor_sync(0xFFFFFFFFu, ph, 1);
        float full = s1 + __shfl_xor_sync(0xFFFFFFFFu, s1, 2);
        float v = fmaxf(fmaf(full, sm->s5[o], sm->b5[o]), 0.0f);
        ss = fmaf(v, v, ss);
        const int rel = o - obase;
        if ((unsigned)rel < 24u) mybase[rel] = v;   // unnormalized, own quarter
    }

    const float rn = rsqrtf(ss);
    float4* o4 = (float4*)mybase;
#pragma unroll
    for (int i = 0; i < 6; ++i) {
        float4 v = o4[i];
        v.x *= rn; v.y *= rn; v.z *= rn; v.w *= rn;
        o4[i] = v;
    }
}

// ---------------------------------------------------------------------------
// launch
// ---------------------------------------------------------------------------
extern "C" void kernel_launch(void* const* d_in, const int* in_sizes, int n_in,
                              void* d_out, int out_size) {
    const float* x   = (const float*)d_in[0];
    const float* w1  = (const float*)d_in[1];
    const float* w2  = (const float*)d_in[2];
    const float* w3  = (const float*)d_in[3];
    const float* w4  = (const float*)d_in[4];
    const float* w5  = (const float*)d_in[5];
    const float* mw  = (const float*)d_in[6];
    const float* mb  = (const float*)d_in[7];
    const float* bn1 = (const float*)d_in[8];
    const float* bn2 = (const float*)d_in[9];
    const float* bn3 = (const float*)d_in[10];
    const float* bn4 = (const float*)d_in[11];
    const float* bn5 = (const float*)d_in[12];

    const size_t knn_smem  = NPTS * 12 + 3 * 64 * 17 * 8 + 256 * QCAP * 4; // ~89.5KB
    const size_t pool_smem = sizeof(SmemPool);            // ~38.8KB
    const size_t gemm_smem = sizeof(SmemGemm);            // ~37.6KB

    cudaFuncSetAttribute(knn_kernel,  cudaFuncAttributeMaxDynamicSharedMemorySize, (int)knn_smem);
    cudaFuncSetAttribute(pool_kernel, cudaFuncAttributeMaxDynamicSharedMemorySize, (int)pool_smem);
    cudaFuncSetAttribute(gemm_kernel, cudaFuncAttributeMaxDynamicSharedMemorySize, (int)gemm_smem);

    dim3 grid(NPTS / 64, BATCH);   // 64 x 8 = 512 blocks
    knn_kernel<<<grid, 256, knn_smem>>>(x);
    pool_kernel<<<grid, 128, pool_smem>>>(x, w1, w2, w3, w4, mw, mb,
                                          bn1, bn2, bn3, bn4);
    gemm_kernel<<<grid, 256, gemm_smem>>>(w5, bn5, (float*)d_out);
}